// round 14
// baseline (speedup 1.0000x reference)
#include <cuda_runtime.h>
#include <cstdint>
#include <math.h>

// ---------------- problem constants ----------------
#define PB 2
#define PN 384
#define PK 384
#define PCZ 128
#define PCOUT 128
#define PBINS 16
#define PCIN (PCZ + PBINS)   // 144

#define F_EPS 1e-8f
#define F_LNEPS 1e-5f
#define F_DMAX 10.0f

// output layout: [Z_c | Z_sem_c | Z_geo_c]
#define SZ_ZC   ((long long)PB * PK * PK * PCOUT)      // 37748736
#define OFF_SEM (SZ_ZC)
#define SZ_SEM  ((long long)PB * PK * PN * PCZ)        // 37748736
#define OFF_GEO (OFF_SEM + SZ_SEM)                     // 75497472

// ---- tf32 mma.sync (sm_80+ baseline feature — works on plain sm_103 target) ----
__device__ __forceinline__ void mma_tf32(float* d, const uint32_t* a, uint32_t b0, uint32_t b1) {
    asm volatile(
        "mma.sync.aligned.m16n8k8.row.col.f32.tf32.tf32.f32 "
        "{%0,%1,%2,%3}, {%4,%5,%6,%7}, {%8,%9}, {%0,%1,%2,%3};"
        : "+f"(d[0]), "+f"(d[1]), "+f"(d[2]), "+f"(d[3])
        : "r"(a[0]), "r"(a[1]), "r"(a[2]), "r"(a[3]), "r"(b0), "r"(b1));
}
__device__ __forceinline__ void split_hl(float v, float& hi, float& lo) {
    hi = __uint_as_float(__float_as_uint(v) & 0xFFFFE000u);
    lo = v - hi;
}

// scratch reductions
__device__ float g_s[PB * PN];    // s[b,n] = mf[b,n] * sum_k A[b,n,k]
__device__ float g_col[PB * PK];  // col[b,a] = sum_n A[b,n,a]*mf[b,n]

// ---------------- K0: row/col reductions ----------------
__global__ void reduce_kernel(const float* __restrict__ A,
                              const float* __restrict__ mask_f) {
    int b = blockIdx.x;
    int t = threadIdx.x;  // 0..383
    if (blockIdx.y == 0) {
        const float* row = A + ((long long)b * PN + t) * PK;
        float s = 0.f;
        for (int k = 0; k < PK; ++k) s += row[k];
        g_s[b * PN + t] = s * mask_f[b * PN + t];
    } else {
        float s = 0.f;
        for (int n = 0; n < PN; ++n)
            s += A[((long long)b * PN + n) * PK + t] * mask_f[b * PN + n];
        g_col[b * PK + t] = s;
    }
}

// ---------------- K1: semantic-coarsening GEMM (R12 known-good) ----------------
#define SEM_BK 32
#define SEM_STR 136
#define SEM_SMEM_BYTES (4 * SEM_BK * SEM_STR * 4)   // 69632

__global__ __launch_bounds__(256, 2)
void sem_gemm_mma(const float* __restrict__ A, const float* __restrict__ Z,
                  const float* __restrict__ mask_f, float* __restrict__ out) {
    extern __shared__ float sm[];
    float* sAhi = sm;
    float* sAlo = sm + SEM_BK * SEM_STR;
    float* sBhi = sm + 2 * SEM_BK * SEM_STR;
    float* sBlo = sm + 3 * SEM_BK * SEM_STR;

    const int m    = blockIdx.x;
    const int aBlk = blockIdx.y;
    const int b    = blockIdx.z;
    const int tid  = threadIdx.x;
    const int w    = tid >> 5, lane = tid & 31;
    const int warpM = w >> 1, warpN = w & 1;
    const int g  = lane >> 2;
    const int kc = lane & 3;

    const float* Ab  = A + (long long)b * PN * PK + aBlk * 128;
    const float* Zb  = Z + (long long)b * PN * PN * PCZ + (long long)m * PCZ;
    const float* mfb = mask_f + b * PN;

    float acc[2][8][4];
#pragma unroll
    for (int mt = 0; mt < 2; ++mt)
#pragma unroll
        for (int nt = 0; nt < 8; ++nt)
#pragma unroll
            for (int q = 0; q < 4; ++q) acc[mt][nt][q] = 0.f;

    const int kloc = tid >> 3;
    const int asub = tid & 7;

    for (int c = 0; c < PK / SEM_BK; ++c) {
        if (c) __syncthreads();
        const int n = c * SEM_BK + kloc;
        const float mf  = mfb[n];
        const float mf2 = mf * mf;
        const float* srcA = Ab + (long long)n * PK;
        const float* srcB = Zb + (long long)n * (PN * PCZ);
#pragma unroll
        for (int j = 0; j < 16; ++j) {
            const int a = asub + 8 * j;
            float hi, lo;
            split_hl(srcA[a] * mf2, hi, lo);
            sAhi[kloc * SEM_STR + a] = hi;
            sAlo[kloc * SEM_STR + a] = lo;
            split_hl(srcB[a], hi, lo);
            sBhi[kloc * SEM_STR + a] = hi;
            sBlo[kloc * SEM_STR + a] = lo;
        }
        __syncthreads();

#pragma unroll
        for (int ks = 0; ks < SEM_BK / 8; ++ks) {
            const int k0 = ks * 8;
            uint32_t ah[2][4], al[2][4];
#pragma unroll
            for (int mt = 0; mt < 2; ++mt) {
                const int r0 = warpM * 32 + mt * 16 + g;
                ah[mt][0] = __float_as_uint(sAhi[(k0 + kc) * SEM_STR + r0]);
                ah[mt][1] = __float_as_uint(sAhi[(k0 + kc) * SEM_STR + r0 + 8]);
                ah[mt][2] = __float_as_uint(sAhi[(k0 + kc + 4) * SEM_STR + r0]);
                ah[mt][3] = __float_as_uint(sAhi[(k0 + kc + 4) * SEM_STR + r0 + 8]);
                al[mt][0] = __float_as_uint(sAlo[(k0 + kc) * SEM_STR + r0]);
                al[mt][1] = __float_as_uint(sAlo[(k0 + kc) * SEM_STR + r0 + 8]);
                al[mt][2] = __float_as_uint(sAlo[(k0 + kc + 4) * SEM_STR + r0]);
                al[mt][3] = __float_as_uint(sAlo[(k0 + kc + 4) * SEM_STR + r0 + 8]);
            }
#pragma unroll
            for (int nt = 0; nt < 8; ++nt) {
                const int cc = warpN * 64 + nt * 8 + g;
                uint32_t bh0 = __float_as_uint(sBhi[(k0 + kc) * SEM_STR + cc]);
                uint32_t bh1 = __float_as_uint(sBhi[(k0 + kc + 4) * SEM_STR + cc]);
                uint32_t bl0 = __float_as_uint(sBlo[(k0 + kc) * SEM_STR + cc]);
                uint32_t bl1 = __float_as_uint(sBlo[(k0 + kc + 4) * SEM_STR + cc]);
#pragma unroll
                for (int mt = 0; mt < 2; ++mt) {
                    mma_tf32(acc[mt][nt], ah[mt], bh0, bh1);
                    mma_tf32(acc[mt][nt], ah[mt], bl0, bl1);
                    mma_tf32(acc[mt][nt], al[mt], bh0, bh1);
                }
            }
        }
    }

    const float smv = g_s[b * PN + m];
    const float num = mfb[m] * smv;
#pragma unroll
    for (int mt = 0; mt < 2; ++mt) {
        const int a0r = aBlk * 128 + warpM * 32 + mt * 16 + g;
        const int a1r = a0r + 8;
        const float f0 = num / fmaxf(g_col[b * PK + a0r] * smv, F_EPS);
        const float f1 = num / fmaxf(g_col[b * PK + a1r] * smv, F_EPS);
        float* d0 = out + OFF_SEM + (((long long)(b * PK + a0r)) * PN + m) * PCZ;
        float* d1 = out + OFF_SEM + (((long long)(b * PK + a1r)) * PN + m) * PCZ;
#pragma unroll
        for (int nt = 0; nt < 8; ++nt) {
            const int cc = warpN * 64 + nt * 8 + 2 * kc;
            float2 v0, v1;
            v0.x = acc[mt][nt][0] * f0; v0.y = acc[mt][nt][1] * f0;
            v1.x = acc[mt][nt][2] * f1; v1.y = acc[mt][nt][3] * f1;
            *(float2*)(d0 + cc) = v0;
            *(float2*)(d1 + cc) = v1;
        }
    }
}

// ---------------- K2: geometry RBF ----------------
__global__ void geo_kernel(const float* __restrict__ mu,
                           const float* __restrict__ mask_c,
                           float* __restrict__ out) {
    int idx = blockIdx.x * 256 + threadIdx.x;
    if (idx >= PB * PK * PK) return;
    int b = idx / (PK * PK);
    int r = idx - b * PK * PK;
    int i = r / PK, j = r - i * PK;
    const float* mi = mu + ((long long)b * PK + i) * 3;
    const float* mj = mu + ((long long)b * PK + j) * 3;
    float dx = mi[0] - mj[0], dy = mi[1] - mj[1], dz = mi[2] - mj[2];
    float d = sqrtf(dx * dx + dy * dy + dz * dz + F_EPS);
    float mc2 = mask_c[b * PK + i] * mask_c[b * PK + j];
    const float width = F_DMAX / (PBINS - 1);
    const float invw  = (PBINS - 1) / F_DMAX;
    float* dst = out + OFF_GEO + (long long)idx * PBINS;
#pragma unroll
    for (int t = 0; t < PBINS; t += 4) {
        float4 v;
        float u;
        u = (d - (t + 0) * width) * invw; v.x = __expf(-0.5f * u * u) * mc2;
        u = (d - (t + 1) * width) * invw; v.y = __expf(-0.5f * u * u) * mc2;
        u = (d - (t + 2) * width) * invw; v.z = __expf(-0.5f * u * u) * mc2;
        u = (d - (t + 3) * width) * invw; v.w = __expf(-0.5f * u * u) * mc2;
        *(float4*)(dst + t) = v;
    }
}

// ---------------- K3: fused MLP, 512 threads, double-buffered staging ----------
// 16 warps (4M x 4N), warp tile 32x32; 1 sync per K-chunk; occ=1 via smem.
#define MLP_STR 136
#define MLP_CH 16
#define MLP_STAGE (MLP_CH * MLP_STR)               // 2176 floats per array
#define MLP_BUF (4 * MLP_STAGE)                    // one stage: Ahi,Alo,Bhi,Blo
#define SG_STRIDE 132
#define SMEM_MLP_FLOATS (2 * MLP_BUF + 128 * SG_STRIDE)   // 34304 floats = 137216 B

__global__ __launch_bounds__(512, 1) void mlp_mma(
    float* __restrict__ out,
    const float* __restrict__ W1, const float* __restrict__ b1,
    const float* __restrict__ lng, const float* __restrict__ lnb,
    const float* __restrict__ W2, const float* __restrict__ b2,
    const float* __restrict__ mask_c) {
    extern __shared__ float sm[];
    float* sG = sm + 2 * MLP_BUF;          // 128 x SG_STRIDE

    const int row0 = blockIdx.x * 128;
    const int tid  = threadIdx.x;
    const int w    = tid >> 5, lane = tid & 31;
    const int warpM = w >> 2, warpN = w & 3;   // 4 x 4
    const int g  = lane >> 2;
    const int kc = lane & 3;
    const float* sem = out + OFF_SEM;
    const float* geo = out + OFF_GEO;

    // staging maps (512 threads)
    const int sr  = tid >> 2;            // 0..127  (X row)
    const int sk4 = (tid & 3) * 4;       // 0,4,8,12 (4 k-values)
    const int ky  = tid >> 5;            // 0..15   (W k-row)
    const int cx4 = (tid & 31) * 4;      // 0..124  (4 cols)

    float acc[2][4][4];
#pragma unroll
    for (int mt = 0; mt < 2; ++mt)
#pragma unroll
        for (int nt = 0; nt < 4; ++nt)
#pragma unroll
            for (int q = 0; q < 4; ++q) acc[mt][nt][q] = 0.f;

    // stage chunk c of X(+W1) into buffer: LDG -> split -> STS
    auto stageX = [&](int c, float* buf) {
        float* sAhi = buf;
        float* sAlo = buf + MLP_STAGE;
        float* sBhi = buf + 2 * MLP_STAGE;
        float* sBlo = buf + 3 * MLP_STAGE;
        const float* p = (c < 8)
            ? sem + (long long)(row0 + sr) * PCZ + c * MLP_CH + sk4
            : geo + (long long)(row0 + sr) * PBINS + sk4;
        float4 v = *(const float4*)p;
        float vv[4] = {v.x, v.y, v.z, v.w};
#pragma unroll
        for (int i = 0; i < 4; ++i) {
            float hi, lo;
            split_hl(vv[i], hi, lo);
            sAhi[(sk4 + i) * MLP_STR + sr] = hi;
            sAlo[(sk4 + i) * MLP_STR + sr] = lo;
        }
        const float* q = W1 + (long long)(c * MLP_CH + ky) * PCOUT + cx4;
        float4 wv = *(const float4*)q;
        float ww[4] = {wv.x, wv.y, wv.z, wv.w};
#pragma unroll
        for (int i = 0; i < 4; ++i) {
            float hi, lo;
            split_hl(ww[i], hi, lo);
            sBhi[ky * MLP_STR + cx4 + i] = hi;
            sBlo[ky * MLP_STR + cx4 + i] = lo;
        }
    };

    auto mmaChunk = [&](float* buf, float a3[2][4][4]) {
        float* sAhi = buf;
        float* sAlo = buf + MLP_STAGE;
        float* sBhi = buf + 2 * MLP_STAGE;
        float* sBlo = buf + 3 * MLP_STAGE;
#pragma unroll
        for (int ks = 0; ks < MLP_CH / 8; ++ks) {
            const int k0 = ks * 8;
            uint32_t ah[2][4], al[2][4];
#pragma unroll
            for (int mt = 0; mt < 2; ++mt) {
                const int r0 = warpM * 32 + mt * 16 + g;
                ah[mt][0] = __float_as_uint(sAhi[(k0 + kc) * MLP_STR + r0]);
                ah[mt][1] = __float_as_uint(sAhi[(k0 + kc) * MLP_STR + r0 + 8]);
                ah[mt][2] = __float_as_uint(sAhi[(k0 + kc + 4) * MLP_STR + r0]);
                ah[mt][3] = __float_as_uint(sAhi[(k0 + kc + 4) * MLP_STR + r0 + 8]);
                al[mt][0] = __float_as_uint(sAlo[(k0 + kc) * MLP_STR + r0]);
                al[mt][1] = __float_as_uint(sAlo[(k0 + kc) * MLP_STR + r0 + 8]);
                al[mt][2] = __float_as_uint(sAlo[(k0 + kc + 4) * MLP_STR + r0]);
                al[mt][3] = __float_as_uint(sAlo[(k0 + kc + 4) * MLP_STR + r0 + 8]);
            }
#pragma unroll
            for (int nt = 0; nt < 4; ++nt) {
                const int cc = warpN * 32 + nt * 8 + g;
                uint32_t bh0 = __float_as_uint(sBhi[(k0 + kc) * MLP_STR + cc]);
                uint32_t bh1 = __float_as_uint(sBhi[(k0 + kc + 4) * MLP_STR + cc]);
                uint32_t bl0 = __float_as_uint(sBlo[(k0 + kc) * MLP_STR + cc]);
                uint32_t bl1 = __float_as_uint(sBlo[(k0 + kc + 4) * MLP_STR + cc]);
#pragma unroll
                for (int mt = 0; mt < 2; ++mt) {
                    mma_tf32(a3[mt][nt], ah[mt], bh0, bh1);
                    mma_tf32(a3[mt][nt], ah[mt], bl0, bl1);
                    mma_tf32(a3[mt][nt], al[mt], bh0, bh1);
                }
            }
        }
    };

    // ---- GEMM1: X[128x144] @ W1[144x128], double-buffered, 1 sync/chunk ----
    stageX(0, sm);
    for (int c = 0; c < PCIN / MLP_CH; ++c) {
        __syncthreads();   // stage(c) visible; MMA(c-1) readers done
        if (c + 1 < PCIN / MLP_CH) stageX(c + 1, sm + ((c + 1) & 1) * MLP_BUF);
        mmaChunk(sm + (c & 1) * MLP_BUF, acc);
    }
    __syncthreads();

    // ---- write h = acc + b1 into sG (fragment layout) ----
#pragma unroll
    for (int mt = 0; mt < 2; ++mt) {
        const int r0 = warpM * 32 + mt * 16 + g;
#pragma unroll
        for (int nt = 0; nt < 4; ++nt) {
            const int cc = warpN * 32 + nt * 8 + 2 * kc;
            float2 bb = *(const float2*)(b1 + cc);
            float2 v0, v1;
            v0.x = acc[mt][nt][0] + bb.x; v0.y = acc[mt][nt][1] + bb.y;
            v1.x = acc[mt][nt][2] + bb.x; v1.y = acc[mt][nt][3] + bb.y;
            *(float2*)&sG[r0 * SG_STRIDE + cc]       = v0;
            *(float2*)&sG[(r0 + 8) * SG_STRIDE + cc] = v1;
        }
    }
    __syncthreads();

    // ---- LayerNorm + SiLU, one thread per row ----
    if (tid < 128) {
        float* gr = &sG[tid * SG_STRIDE];
        float s = 0.f;
#pragma unroll 8
        for (int c = 0; c < 128; ++c) s += gr[c];
        float mu = s * (1.f / 128.f);
        float vs = 0.f;
#pragma unroll 8
        for (int c = 0; c < 128; ++c) { float dd = gr[c] - mu; vs = fmaf(dd, dd, vs); }
        float rstd = rsqrtf(vs * (1.f / 128.f) + F_LNEPS);
#pragma unroll 8
        for (int c = 0; c < 128; ++c) {
            float x = (gr[c] - mu) * rstd * lng[c] + lnb[c];
            gr[c] = x / (1.f + __expf(-x));
        }
    }

    // stage chunk c of silu(h)(+W2)
    auto stageH = [&](int c, float* buf) {
        float* sAhi = buf;
        float* sAlo = buf + MLP_STAGE;
        float* sBhi = buf + 2 * MLP_STAGE;
        float* sBlo = buf + 3 * MLP_STAGE;
        const float* p = &sG[sr * SG_STRIDE + c * MLP_CH + sk4];
#pragma unroll
        for (int i = 0; i < 4; ++i) {
            float hi, lo;
            split_hl(p[i], hi, lo);
            sAhi[(sk4 + i) * MLP_STR + sr] = hi;
            sAlo[(sk4 + i) * MLP_STR + sr] = lo;
        }
        const float* q = W2 + (long long)(c * MLP_CH + ky) * PCOUT + cx4;
        float4 wv = *(const float4*)q;
        float ww[4] = {wv.x, wv.y, wv.z, wv.w};
#pragma unroll
        for (int i = 0; i < 4; ++i) {
            float hi, lo;
            split_hl(ww[i], hi, lo);
            sBhi[ky * MLP_STR + cx4 + i] = hi;
            sBlo[ky * MLP_STR + cx4 + i] = lo;
        }
    };

    // ---- GEMM2: silu(h)[128x128] @ W2[128x128] ----
    float acc2[2][4][4];
#pragma unroll
    for (int mt = 0; mt < 2; ++mt)
#pragma unroll
        for (int nt = 0; nt < 4; ++nt)
#pragma unroll
            for (int q = 0; q < 4; ++q) acc2[mt][nt][q] = 0.f;

    __syncthreads();       // LN done; stage buffers free
    stageH(0, sm);
    for (int c = 0; c < PCOUT / MLP_CH; ++c) {
        __syncthreads();
        if (c + 1 < PCOUT / MLP_CH) stageH(c + 1, sm + ((c + 1) & 1) * MLP_BUF);
        mmaChunk(sm + (c & 1) * MLP_BUF, acc2);
    }

    // ---- epilogue: +b2, *mc2, write Z_c ----
#pragma unroll
    for (int mt = 0; mt < 2; ++mt) {
        const int rg0 = row0 + warpM * 32 + mt * 16 + g;
        const int rg1 = rg0 + 8;
        int bb0 = rg0 / (PK * PK), rr0 = rg0 - bb0 * PK * PK;
        int bb1 = rg1 / (PK * PK), rr1 = rg1 - bb1 * PK * PK;
        int i0 = rr0 / PK, j0 = rr0 - i0 * PK;
        int i1 = rr1 / PK, j1 = rr1 - i1 * PK;
        const float mc0 = mask_c[bb0 * PK + i0] * mask_c[bb0 * PK + j0];
        const float mc1 = mask_c[bb1 * PK + i1] * mask_c[bb1 * PK + j1];
        float* d0 = out + (long long)rg0 * PCOUT;
        float* d1 = out + (long long)rg1 * PCOUT;
#pragma unroll
        for (int nt = 0; nt < 4; ++nt) {
            const int cc = warpN * 32 + nt * 8 + 2 * kc;
            float2 bb = *(const float2*)(b2 + cc);
            float2 v0, v1;
            v0.x = (acc2[mt][nt][0] + bb.x) * mc0; v0.y = (acc2[mt][nt][1] + bb.y) * mc0;
            v1.x = (acc2[mt][nt][2] + bb.x) * mc1; v1.y = (acc2[mt][nt][3] + bb.y) * mc1;
            *(float2*)(d0 + cc) = v0;
            *(float2*)(d1 + cc) = v1;
        }
    }
}

// ---------------- launch ----------------
extern "C" void kernel_launch(void* const* d_in, const int* in_sizes, int n_in,
                              void* d_out, int out_size) {
    const float* A      = (const float*)d_in[0];
    const float* Zf     = (const float*)d_in[1];
    const float* mu     = (const float*)d_in[2];
    const float* mask_f = (const float*)d_in[3];
    const float* mask_c = (const float*)d_in[4];
    const float* W1     = (const float*)d_in[5];
    const float* b1     = (const float*)d_in[6];
    const float* lng    = (const float*)d_in[7];
    const float* lnb    = (const float*)d_in[8];
    const float* W2     = (const float*)d_in[9];
    const float* b2     = (const float*)d_in[10];
    float* out = (float*)d_out;

    const int smem_mlp = SMEM_MLP_FLOATS * (int)sizeof(float);
    cudaFuncSetAttribute(mlp_mma, cudaFuncAttributeMaxDynamicSharedMemorySize, smem_mlp);
    cudaFuncSetAttribute(sem_gemm_mma, cudaFuncAttributeMaxDynamicSharedMemorySize, SEM_SMEM_BYTES);

    reduce_kernel<<<dim3(PB, 2), PK>>>(A, mask_f);
    sem_gemm_mma<<<dim3(PN, 3, PB), 256, SEM_SMEM_BYTES>>>(A, Zf, mask_f, out);
    geo_kernel<<<(PB * PK * PK + 255) / 256, 256>>>(mu, mask_c, out);
    mlp_mma<<<PB * PK * PK / 128, 512, smem_mlp>>>(out, W1, b1, lng, lnb, W2, b2, mask_c);
}

// round 16
// speedup vs baseline: 1.2300x; 1.2300x over previous
#include <cuda_runtime.h>
#include <cstdint>
#include <math.h>

// ---------------- problem constants ----------------
#define PB 2
#define PN 384
#define PK 384
#define PCZ 128
#define PCOUT 128
#define PBINS 16
#define PCIN (PCZ + PBINS)   // 144

#define F_EPS 1e-8f
#define F_LNEPS 1e-5f
#define F_DMAX 10.0f

// output layout: [Z_c | Z_sem_c | Z_geo_c]
#define SZ_ZC   ((long long)PB * PK * PK * PCOUT)      // 37748736
#define OFF_SEM (SZ_ZC)
#define SZ_SEM  ((long long)PB * PK * PN * PCZ)        // 37748736
#define OFF_GEO (OFF_SEM + SZ_SEM)                     // 75497472

// ---- tf32 mma.sync (sm_80+ baseline — works on plain sm_103 target) ----
__device__ __forceinline__ void mma_tf32(float* d, const uint32_t* a, uint32_t b0, uint32_t b1) {
    asm volatile(
        "mma.sync.aligned.m16n8k8.row.col.f32.tf32.tf32.f32 "
        "{%0,%1,%2,%3}, {%4,%5,%6,%7}, {%8,%9}, {%0,%1,%2,%3};"
        : "+f"(d[0]), "+f"(d[1]), "+f"(d[2]), "+f"(d[3])
        : "r"(a[0]), "r"(a[1]), "r"(a[2]), "r"(a[3]), "r"(b0), "r"(b1));
}
__device__ __forceinline__ void split_hl(float v, float& hi, float& lo) {
    hi = __uint_as_float(__float_as_uint(v) & 0xFFFFE000u);
    lo = v - hi;
}
// ---- cp.async helpers (sm_80 baseline) ----
__device__ __forceinline__ void cp16(void* smem_ptr, const void* gptr) {
    uint32_t s = (uint32_t)__cvta_generic_to_shared(smem_ptr);
    asm volatile("cp.async.cg.shared.global [%0], [%1], 16;" :: "r"(s), "l"(gptr));
}
#define CP_COMMIT() asm volatile("cp.async.commit_group;" ::: "memory")
#define CP_WAIT0()  asm volatile("cp.async.wait_group 0;" ::: "memory")

// scratch reductions
__device__ float g_s[PB * PN];    // s[b,n] = mf[b,n] * sum_k A[b,n,k]
__device__ float g_col[PB * PK];  // col[b,a] = sum_n A[b,n,a]*mf[b,n]

// ---------------- K0: row/col reductions ----------------
__global__ void reduce_kernel(const float* __restrict__ A,
                              const float* __restrict__ mask_f) {
    int b = blockIdx.x;
    int t = threadIdx.x;  // 0..383
    if (blockIdx.y == 0) {
        const float* row = A + ((long long)b * PN + t) * PK;
        float s = 0.f;
        for (int k = 0; k < PK; ++k) s += row[k];
        g_s[b * PN + t] = s * mask_f[b * PN + t];
    } else {
        float s = 0.f;
        for (int n = 0; n < PN; ++n)
            s += A[((long long)b * PN + n) * PK + t] * mask_f[b * PN + n];
        g_col[b * PK + t] = s;
    }
}

// ---------------- K1: semantic-coarsening GEMM, cp.async-pipelined ----------
// R12 MMA structure; raw A/B chunk buffers filled by cp.async overlap MMA.
#define SEM_BK 32
#define SEM_STR 136
#define SEM_RAWSTR 132
#define SEM_STAGE_F (4 * SEM_BK * SEM_STR)              // 17408 floats
#define SEM_RAW_F (SEM_BK * SEM_RAWSTR)                 // 4224 floats each
#define SEM_SMEM_BYTES ((SEM_STAGE_F + 2 * SEM_RAW_F) * 4)   // 103424 B

__global__ __launch_bounds__(256, 2)
void sem_gemm_mma(const float* __restrict__ A, const float* __restrict__ Z,
                  const float* __restrict__ mask_f, float* __restrict__ out) {
    extern __shared__ float sm[];
    float* sAhi = sm;
    float* sAlo = sm + SEM_BK * SEM_STR;
    float* sBhi = sm + 2 * SEM_BK * SEM_STR;
    float* sBlo = sm + 3 * SEM_BK * SEM_STR;
    float* rawA = sm + SEM_STAGE_F;
    float* rawB = rawA + SEM_RAW_F;

    const int m    = blockIdx.x;
    const int aBlk = blockIdx.y;
    const int b    = blockIdx.z;
    const int tid  = threadIdx.x;
    const int w    = tid >> 5, lane = tid & 31;
    const int warpM = w >> 1, warpN = w & 1;
    const int g  = lane >> 2;
    const int kc = lane & 3;

    const float* Ab  = A + (long long)b * PN * PK + aBlk * 128;
    const float* Zb  = Z + (long long)b * PN * PN * PCZ + (long long)m * PCZ;
    const float* mfb = mask_f + b * PN;

    float acc[2][8][4];
#pragma unroll
    for (int mt = 0; mt < 2; ++mt)
#pragma unroll
        for (int nt = 0; nt < 8; ++nt)
#pragma unroll
            for (int q = 0; q < 4; ++q) acc[mt][nt][q] = 0.f;

    const int kloc = tid >> 3;     // 0..31 staging row
    const int asub = tid & 7;
    // cp.async fill map: row = tid>>3 (0..31), col-chunk base = tid&7, 4 chunks of 4 floats
    auto fill_chunk = [&](int c) {
        const int r = tid >> 3;
        const int n = c * SEM_BK + r;
        const float* gA = Ab + (long long)n * PK;
        const float* gB = Zb + (long long)n * (PN * PCZ);
#pragma unroll
        for (int i = 0; i < 4; ++i) {
            const int col = (asub + 8 * i) * 4;
            cp16(&rawA[r * SEM_RAWSTR + col], gA + col);
            cp16(&rawB[r * SEM_RAWSTR + col], gB + col);
        }
    };

    fill_chunk(0);
    CP_COMMIT();

    for (int c = 0; c < PK / SEM_BK; ++c) {
        CP_WAIT0();
        __syncthreads();            // raw(c) visible; MMA(c-1) readers done
        const float mf  = mfb[c * SEM_BK + kloc];
        const float mf2 = mf * mf;
#pragma unroll
        for (int j = 0; j < 16; ++j) {
            const int a = asub + 8 * j;
            float hi, lo;
            split_hl(rawA[kloc * SEM_RAWSTR + a] * mf2, hi, lo);
            sAhi[kloc * SEM_STR + a] = hi;
            sAlo[kloc * SEM_STR + a] = lo;
            split_hl(rawB[kloc * SEM_RAWSTR + a], hi, lo);
            sBhi[kloc * SEM_STR + a] = hi;
            sBlo[kloc * SEM_STR + a] = lo;
        }
        __syncthreads();            // staging ready; raw reads done
        if (c + 1 < PK / SEM_BK) { fill_chunk(c + 1); CP_COMMIT(); }

#pragma unroll
        for (int ks = 0; ks < SEM_BK / 8; ++ks) {
            const int k0 = ks * 8;
            uint32_t ah[2][4], al[2][4];
#pragma unroll
            for (int mt = 0; mt < 2; ++mt) {
                const int r0 = warpM * 32 + mt * 16 + g;
                ah[mt][0] = __float_as_uint(sAhi[(k0 + kc) * SEM_STR + r0]);
                ah[mt][1] = __float_as_uint(sAhi[(k0 + kc) * SEM_STR + r0 + 8]);
                ah[mt][2] = __float_as_uint(sAhi[(k0 + kc + 4) * SEM_STR + r0]);
                ah[mt][3] = __float_as_uint(sAhi[(k0 + kc + 4) * SEM_STR + r0 + 8]);
                al[mt][0] = __float_as_uint(sAlo[(k0 + kc) * SEM_STR + r0]);
                al[mt][1] = __float_as_uint(sAlo[(k0 + kc) * SEM_STR + r0 + 8]);
                al[mt][2] = __float_as_uint(sAlo[(k0 + kc + 4) * SEM_STR + r0]);
                al[mt][3] = __float_as_uint(sAlo[(k0 + kc + 4) * SEM_STR + r0 + 8]);
            }
#pragma unroll
            for (int nt = 0; nt < 8; ++nt) {
                const int cc = warpN * 64 + nt * 8 + g;
                uint32_t bh0 = __float_as_uint(sBhi[(k0 + kc) * SEM_STR + cc]);
                uint32_t bh1 = __float_as_uint(sBhi[(k0 + kc + 4) * SEM_STR + cc]);
                uint32_t bl0 = __float_as_uint(sBlo[(k0 + kc) * SEM_STR + cc]);
                uint32_t bl1 = __float_as_uint(sBlo[(k0 + kc + 4) * SEM_STR + cc]);
#pragma unroll
                for (int mt = 0; mt < 2; ++mt) {
                    mma_tf32(acc[mt][nt], ah[mt], bh0, bh1);
                    mma_tf32(acc[mt][nt], ah[mt], bl0, bl1);
                    mma_tf32(acc[mt][nt], al[mt], bh0, bh1);
                }
            }
        }
    }

    const float smv = g_s[b * PN + m];
    const float num = mfb[m] * smv;
#pragma unroll
    for (int mt = 0; mt < 2; ++mt) {
        const int a0r = aBlk * 128 + warpM * 32 + mt * 16 + g;
        const int a1r = a0r + 8;
        const float f0 = num / fmaxf(g_col[b * PK + a0r] * smv, F_EPS);
        const float f1 = num / fmaxf(g_col[b * PK + a1r] * smv, F_EPS);
        float* d0 = out + OFF_SEM + (((long long)(b * PK + a0r)) * PN + m) * PCZ;
        float* d1 = out + OFF_SEM + (((long long)(b * PK + a1r)) * PN + m) * PCZ;
#pragma unroll
        for (int nt = 0; nt < 8; ++nt) {
            const int cc = warpN * 64 + nt * 8 + 2 * kc;
            float2 v0, v1;
            v0.x = acc[mt][nt][0] * f0; v0.y = acc[mt][nt][1] * f0;
            v1.x = acc[mt][nt][2] * f1; v1.y = acc[mt][nt][3] * f1;
            *(float2*)(d0 + cc) = v0;
            *(float2*)(d1 + cc) = v1;
        }
    }
}

// ---------------- K2: geometry RBF ----------------
__global__ void geo_kernel(const float* __restrict__ mu,
                           const float* __restrict__ mask_c,
                           float* __restrict__ out) {
    int idx = blockIdx.x * 256 + threadIdx.x;
    if (idx >= PB * PK * PK) return;
    int b = idx / (PK * PK);
    int r = idx - b * PK * PK;
    int i = r / PK, j = r - i * PK;
    const float* mi = mu + ((long long)b * PK + i) * 3;
    const float* mj = mu + ((long long)b * PK + j) * 3;
    float dx = mi[0] - mj[0], dy = mi[1] - mj[1], dz = mi[2] - mj[2];
    float d = sqrtf(dx * dx + dy * dy + dz * dz + F_EPS);
    float mc2 = mask_c[b * PK + i] * mask_c[b * PK + j];
    const float width = F_DMAX / (PBINS - 1);
    const float invw  = (PBINS - 1) / F_DMAX;
    float* dst = out + OFF_GEO + (long long)idx * PBINS;
#pragma unroll
    for (int t = 0; t < PBINS; t += 4) {
        float4 v;
        float u;
        u = (d - (t + 0) * width) * invw; v.x = __expf(-0.5f * u * u) * mc2;
        u = (d - (t + 1) * width) * invw; v.y = __expf(-0.5f * u * u) * mc2;
        u = (d - (t + 2) * width) * invw; v.z = __expf(-0.5f * u * u) * mc2;
        u = (d - (t + 3) * width) * invw; v.w = __expf(-0.5f * u * u) * mc2;
        *(float4*)(dst + t) = v;
    }
}

// ---------------- K3: fused MLP, R12 shape + cp.async prefetch of X ----------
#define MLP_STR 136
#define MLP_CH 16
#define MLP_STAGE (MLP_CH * MLP_STR)               // 2176 floats per array
#define MLP_RAWSTR 20
#define MLP_RAW_F (128 * MLP_RAWSTR)               // 2560 floats
#define SG_STRIDE 132
#define SMEM_MLP_FLOATS (4 * MLP_STAGE + 128 * SG_STRIDE + MLP_RAW_F)  // 28160 f = 112640 B

__global__ __launch_bounds__(256, 2) void mlp_mma(
    float* __restrict__ out,
    const float* __restrict__ W1, const float* __restrict__ b1,
    const float* __restrict__ lng, const float* __restrict__ lnb,
    const float* __restrict__ W2, const float* __restrict__ b2,
    const float* __restrict__ mask_c) {
    extern __shared__ float sm[];
    float* sAhi = sm;
    float* sAlo = sm + MLP_STAGE;
    float* sBhi = sm + 2 * MLP_STAGE;
    float* sBlo = sm + 3 * MLP_STAGE;
    float* sG   = sm + 4 * MLP_STAGE;          // 128 x SG_STRIDE
    float* rawX = sG + 128 * SG_STRIDE;        // 128 x MLP_RAWSTR

    const int row0 = blockIdx.x * 128;
    const int tid  = threadIdx.x;
    const int w    = tid >> 5, lane = tid & 31;
    const int warpM = w >> 1, warpN = w & 1;
    const int g  = lane >> 2;
    const int kc = lane & 3;
    const float* sem = out + OFF_SEM;
    const float* geo = out + OFF_GEO;

    const int sr = tid >> 1;            // 0..127 row
    const int sk = (tid & 1) * 8;       // 0 or 8
    const int ky = tid >> 4, cx = tid & 15;   // W staging map

    float acc[2][8][4];
#pragma unroll
    for (int mt = 0; mt < 2; ++mt)
#pragma unroll
        for (int nt = 0; nt < 8; ++nt)
#pragma unroll
            for (int q = 0; q < 4; ++q) acc[mt][nt][q] = 0.f;

    // cp.async fill of X chunk c: thread t covers row r = t>>1, 2x16B chunks
    auto fillX = [&](int c) {
        const int r = tid >> 1;
        const int j = tid & 1;
        const float* p = (c < 8)
            ? sem + (long long)(row0 + r) * PCZ + c * MLP_CH
            : geo + (long long)(row0 + r) * PBINS;
        cp16(&rawX[r * MLP_RAWSTR + j * 4],     p + j * 4);
        cp16(&rawX[r * MLP_RAWSTR + j * 4 + 8], p + j * 4 + 8);
    };

    fillX(0);
    CP_COMMIT();

    // ---- GEMM1: X[128x144] @ W1[144x128] ----
    for (int c = 0; c < PCIN / MLP_CH; ++c) {
        CP_WAIT0();
        __syncthreads();
        // stage X from rawX (split), W1 from global (L1/L2-hot)
        {
            const float* p = &rawX[sr * MLP_RAWSTR + sk];
#pragma unroll
            for (int i = 0; i < 8; ++i) {
                float hi, lo;
                split_hl(p[i], hi, lo);
                sAhi[(sk + i) * MLP_STR + sr] = hi;
                sAlo[(sk + i) * MLP_STR + sr] = lo;
            }
            const float* q = W1 + (long long)(c * MLP_CH + ky) * PCOUT + cx * 8;
            float4 w0 = *(const float4*)q;
            float4 w1 = *(const float4*)(q + 4);
            float ww[8] = {w0.x, w0.y, w0.z, w0.w, w1.x, w1.y, w1.z, w1.w};
#pragma unroll
            for (int i = 0; i < 8; ++i) {
                float hi, lo;
                split_hl(ww[i], hi, lo);
                sBhi[ky * MLP_STR + cx * 8 + i] = hi;
                sBlo[ky * MLP_STR + cx * 8 + i] = lo;
            }
        }
        __syncthreads();
        if (c + 1 < PCIN / MLP_CH) { fillX(c + 1); CP_COMMIT(); }

#pragma unroll
        for (int ks = 0; ks < MLP_CH / 8; ++ks) {
            const int k0 = ks * 8;
            uint32_t ah[2][4], al[2][4];
#pragma unroll
            for (int mt = 0; mt < 2; ++mt) {
                const int r0 = warpM * 32 + mt * 16 + g;
                ah[mt][0] = __float_as_uint(sAhi[(k0 + kc) * MLP_STR + r0]);
                ah[mt][1] = __float_as_uint(sAhi[(k0 + kc) * MLP_STR + r0 + 8]);
                ah[mt][2] = __float_as_uint(sAhi[(k0 + kc + 4) * MLP_STR + r0]);
                ah[mt][3] = __float_as_uint(sAhi[(k0 + kc + 4) * MLP_STR + r0 + 8]);
                al[mt][0] = __float_as_uint(sAlo[(k0 + kc) * MLP_STR + r0]);
                al[mt][1] = __float_as_uint(sAlo[(k0 + kc) * MLP_STR + r0 + 8]);
                al[mt][2] = __float_as_uint(sAlo[(k0 + kc + 4) * MLP_STR + r0]);
                al[mt][3] = __float_as_uint(sAlo[(k0 + kc + 4) * MLP_STR + r0 + 8]);
            }
#pragma unroll
            for (int nt = 0; nt < 8; ++nt) {
                const int cc = warpN * 64 + nt * 8 + g;
                uint32_t bh0 = __float_as_uint(sBhi[(k0 + kc) * MLP_STR + cc]);
                uint32_t bh1 = __float_as_uint(sBhi[(k0 + kc + 4) * MLP_STR + cc]);
                uint32_t bl0 = __float_as_uint(sBlo[(k0 + kc) * MLP_STR + cc]);
                uint32_t bl1 = __float_as_uint(sBlo[(k0 + kc + 4) * MLP_STR + cc]);
#pragma unroll
                for (int mt = 0; mt < 2; ++mt) {
                    mma_tf32(acc[mt][nt], ah[mt], bh0, bh1);
                    mma_tf32(acc[mt][nt], ah[mt], bl0, bl1);
                    mma_tf32(acc[mt][nt], al[mt], bh0, bh1);
                }
            }
        }
    }
    __syncthreads();

    // ---- write h = acc + b1 into sG (fragment layout) ----
#pragma unroll
    for (int mt = 0; mt < 2; ++mt) {
        const int r0 = warpM * 32 + mt * 16 + g;
#pragma unroll
        for (int nt = 0; nt < 8; ++nt) {
            const int cc = warpN * 64 + nt * 8 + 2 * kc;
            float2 bb = *(const float2*)(b1 + cc);
            float2 v0, v1;
            v0.x = acc[mt][nt][0] + bb.x; v0.y = acc[mt][nt][1] + bb.y;
            v1.x = acc[mt][nt][2] + bb.x; v1.y = acc[mt][nt][3] + bb.y;
            *(float2*)&sG[r0 * SG_STRIDE + cc]       = v0;
            *(float2*)&sG[(r0 + 8) * SG_STRIDE + cc] = v1;
        }
    }
    __syncthreads();

    // ---- LayerNorm + SiLU, one thread per row ----
    if (tid < 128) {
        float* gr = &sG[tid * SG_STRIDE];
        float s = 0.f;
#pragma unroll 8
        for (int c = 0; c < 128; ++c) s += gr[c];
        float mu = s * (1.f / 128.f);
        float vs = 0.f;
#pragma unroll 8
        for (int c = 0; c < 128; ++c) { float dd = gr[c] - mu; vs = fmaf(dd, dd, vs); }
        float rstd = rsqrtf(vs * (1.f / 128.f) + F_LNEPS);
#pragma unroll 8
        for (int c = 0; c < 128; ++c) {
            float x = (gr[c] - mu) * rstd * lng[c] + lnb[c];
            gr[c] = x / (1.f + __expf(-x));
        }
    }

    // ---- GEMM2: silu(h)[128x128] @ W2[128x128] (serial; A from smem) ----
    float acc2[2][8][4];
#pragma unroll
    for (int mt = 0; mt < 2; ++mt)
#pragma unroll
        for (int nt = 0; nt < 8; ++nt)
#pragma unroll
            for (int q = 0; q < 4; ++q) acc2[mt][nt][q] = 0.f;

    for (int c = 0; c < PCOUT / MLP_CH; ++c) {
        __syncthreads();
        {
            const float* p = &sG[sr * SG_STRIDE + c * MLP_CH + sk];
#pragma unroll
            for (int i = 0; i < 8; ++i) {
                float hi, lo;
                split_hl(p[i], hi, lo);
                sAhi[(sk + i) * MLP_STR + sr] = hi;
                sAlo[(sk + i) * MLP_STR + sr] = lo;
            }
            const float* q = W2 + (long long)(c * MLP_CH + ky) * PCOUT + cx * 8;
            float4 w0 = *(const float4*)q;
            float4 w1 = *(const float4*)(q + 4);
            float ww[8] = {w0.x, w0.y, w0.z, w0.w, w1.x, w1.y, w1.z, w1.w};
#pragma unroll
            for (int i = 0; i < 8; ++i) {
                float hi, lo;
                split_hl(ww[i], hi, lo);
                sBhi[ky * MLP_STR + cx * 8 + i] = hi;
                sBlo[ky * MLP_STR + cx * 8 + i] = lo;
            }
        }
        __syncthreads();
#pragma unroll
        for (int ks = 0; ks < MLP_CH / 8; ++ks) {
            const int k0 = ks * 8;
            uint32_t ah[2][4], al[2][4];
#pragma unroll
            for (int mt = 0; mt < 2; ++mt) {
                const int r0 = warpM * 32 + mt * 16 + g;
                ah[mt][0] = __float_as_uint(sAhi[(k0 + kc) * MLP_STR + r0]);
                ah[mt][1] = __float_as_uint(sAhi[(k0 + kc) * MLP_STR + r0 + 8]);
                ah[mt][2] = __float_as_uint(sAhi[(k0 + kc + 4) * MLP_STR + r0]);
                ah[mt][3] = __float_as_uint(sAhi[(k0 + kc + 4) * MLP_STR + r0 + 8]);
                al[mt][0] = __float_as_uint(sAlo[(k0 + kc) * MLP_STR + r0]);
                al[mt][1] = __float_as_uint(sAlo[(k0 + kc) * MLP_STR + r0 + 8]);
                al[mt][2] = __float_as_uint(sAlo[(k0 + kc + 4) * MLP_STR + r0]);
                al[mt][3] = __float_as_uint(sAlo[(k0 + kc + 4) * MLP_STR + r0 + 8]);
            }
#pragma unroll
            for (int nt = 0; nt < 8; ++nt) {
                const int cc = warpN * 64 + nt * 8 + g;
                uint32_t bh0 = __float_as_uint(sBhi[(k0 + kc) * MLP_STR + cc]);
                uint32_t bh1 = __float_as_uint(sBhi[(k0 + kc + 4) * MLP_STR + cc]);
                uint32_t bl0 = __float_as_uint(sBlo[(k0 + kc) * MLP_STR + cc]);
                uint32_t bl1 = __float_as_uint(sBlo[(k0 + kc + 4) * MLP_STR + cc]);
#pragma unroll
                for (int mt = 0; mt < 2; ++mt) {
                    mma_tf32(acc2[mt][nt], ah[mt], bh0, bh1);
                    mma_tf32(acc2[mt][nt], ah[mt], bl0, bl1);
                    mma_tf32(acc2[mt][nt], al[mt], bh0, bh1);
                }
            }
        }
    }

    // ---- epilogue: +b2, *mc2, write Z_c ----
#pragma unroll
    for (int mt = 0; mt < 2; ++mt) {
        const int rg0 = row0 + warpM * 32 + mt * 16 + g;
        const int rg1 = rg0 + 8;
        int bb0 = rg0 / (PK * PK), rr0 = rg0 - bb0 * PK * PK;
        int bb1 = rg1 / (PK * PK), rr1 = rg1 - bb1 * PK * PK;
        int i0 = rr0 / PK, j0 = rr0 - i0 * PK;
        int i1 = rr1 / PK, j1 = rr1 - i1 * PK;
        const float mc0 = mask_c[bb0 * PK + i0] * mask_c[bb0 * PK + j0];
        const float mc1 = mask_c[bb1 * PK + i1] * mask_c[bb1 * PK + j1];
        float* d0 = out + (long long)rg0 * PCOUT;
        float* d1 = out + (long long)rg1 * PCOUT;
#pragma unroll
        for (int nt = 0; nt < 8; ++nt) {
            const int cc = warpN * 64 + nt * 8 + 2 * kc;
            float2 bb = *(const float2*)(b2 + cc);
            float2 v0, v1;
            v0.x = (acc2[mt][nt][0] + bb.x) * mc0; v0.y = (acc2[mt][nt][1] + bb.y) * mc0;
            v1.x = (acc2[mt][nt][2] + bb.x) * mc1; v1.y = (acc2[mt][nt][3] + bb.y) * mc1;
            *(float2*)(d0 + cc) = v0;
            *(float2*)(d1 + cc) = v1;
        }
    }
}

// ---------------- launch ----------------
extern "C" void kernel_launch(void* const* d_in, const int* in_sizes, int n_in,
                              void* d_out, int out_size) {
    const float* A      = (const float*)d_in[0];
    const float* Zf     = (const float*)d_in[1];
    const float* mu     = (const float*)d_in[2];
    const float* mask_f = (const float*)d_in[3];
    const float* mask_c = (const float*)d_in[4];
    const float* W1     = (const float*)d_in[5];
    const float* b1     = (const float*)d_in[6];
    const float* lng    = (const float*)d_in[7];
    const float* lnb    = (const float*)d_in[8];
    const float* W2     = (const float*)d_in[9];
    const float* b2     = (const float*)d_in[10];
    float* out = (float*)d_out;

    const int smem_mlp = SMEM_MLP_FLOATS * (int)sizeof(float);
    cudaFuncSetAttribute(mlp_mma, cudaFuncAttributeMaxDynamicSharedMemorySize, smem_mlp);
    cudaFuncSetAttribute(sem_gemm_mma, cudaFuncAttributeMaxDynamicSharedMemorySize, SEM_SMEM_BYTES);

    reduce_kernel<<<dim3(PB, 2), PK>>>(A, mask_f);
    sem_gemm_mma<<<dim3(PN, 3, PB), 256, SEM_SMEM_BYTES>>>(A, Zf, mask_f, out);
    geo_kernel<<<(PB * PK * PK + 255) / 256, 256>>>(mu, mask_c, out);
    mlp_mma<<<PB * PK * PK / 128, 256, smem_mlp>>>(out, W1, b1, lng, lnb, W2, b2, mask_c);
}

// round 17
// speedup vs baseline: 1.5310x; 1.2448x over previous
#include <cuda_runtime.h>
#include <cstdint>
#include <math.h>

// ---------------- problem constants ----------------
#define PB 2
#define PN 384
#define PK 384
#define PCZ 128
#define PCOUT 128
#define PBINS 16
#define PCIN (PCZ + PBINS)   // 144

#define F_EPS 1e-8f
#define F_LNEPS 1e-5f
#define F_DMAX 10.0f

// output layout: [Z_c | Z_sem_c | Z_geo_c]
#define SZ_ZC   ((long long)PB * PK * PK * PCOUT)      // 37748736
#define OFF_SEM (SZ_ZC)
#define SZ_SEM  ((long long)PB * PK * PN * PCZ)        // 37748736
#define OFF_GEO (OFF_SEM + SZ_SEM)                     // 75497472

// ---- tf32 mma.sync (sm_80+ baseline — works on plain sm_103 target) ----
__device__ __forceinline__ void mma_tf32(float* d, const uint32_t* a, uint32_t b0, uint32_t b1) {
    asm volatile(
        "mma.sync.aligned.m16n8k8.row.col.f32.tf32.tf32.f32 "
        "{%0,%1,%2,%3}, {%4,%5,%6,%7}, {%8,%9}, {%0,%1,%2,%3};"
        : "+f"(d[0]), "+f"(d[1]), "+f"(d[2]), "+f"(d[3])
        : "r"(a[0]), "r"(a[1]), "r"(a[2]), "r"(a[3]), "r"(b0), "r"(b1));
}
// exact split: v = hi + lo, hi is tf32-representable (truncate to 13-bit mantissa)
__device__ __forceinline__ void split_hl(float v, float& hi, float& lo) {
    hi = __uint_as_float(__float_as_uint(v) & 0xFFFFE000u);
    lo = v - hi;
}
// round-to-nearest tf32 (unbiased, <=0.5 ulp)
__device__ __forceinline__ float to_tf32_rn(float v) {
    uint32_t b = __float_as_uint(v) + 0x1000u;
    return __uint_as_float(b & 0xFFFFE000u);
}
// ---- cp.async helpers (sm_80 baseline) ----
__device__ __forceinline__ void cp16(void* smem_ptr, const void* gptr) {
    uint32_t s = (uint32_t)__cvta_generic_to_shared(smem_ptr);
    asm volatile("cp.async.cg.shared.global [%0], [%1], 16;" :: "r"(s), "l"(gptr));
}
#define CP_COMMIT() asm volatile("cp.async.commit_group;" ::: "memory")
#define CP_WAIT0()  asm volatile("cp.async.wait_group 0;" ::: "memory")

// scratch reductions
__device__ float g_s[PB * PN];    // s[b,n] = mf[b,n] * sum_k A[b,n,k]
__device__ float g_col[PB * PK];  // col[b,a] = sum_n A[b,n,a]*mf[b,n]

// ---------------- K0: row/col reductions ----------------
__global__ void reduce_kernel(const float* __restrict__ A,
                              const float* __restrict__ mask_f) {
    int b = blockIdx.x;
    int t = threadIdx.x;  // 0..383
    if (blockIdx.y == 0) {
        const float* row = A + ((long long)b * PN + t) * PK;
        float s = 0.f;
        for (int k = 0; k < PK; ++k) s += row[k];
        g_s[b * PN + t] = s * mask_f[b * PN + t];
    } else {
        float s = 0.f;
        for (int n = 0; n < PN; ++n)
            s += A[((long long)b * PN + n) * PK + t] * mask_f[b * PN + n];
        g_col[b * PK + t] = s;
    }
}

// ---------------- K1: semantic-coarsening GEMM, cp.async + 2-MMA split ------
// A split exactly (hi/lo), B=Z rounded to tf32 (rn). acc = Ah*B + Al*B.
#define SEM_BK 32
#define SEM_STR 136
#define SEM_RAWSTR 132
#define SEM_STAGE_F (3 * SEM_BK * SEM_STR)              // 13056 floats
#define SEM_RAW_F (SEM_BK * SEM_RAWSTR)                 // 4224 floats each
#define SEM_SMEM_BYTES ((SEM_STAGE_F + 2 * SEM_RAW_F) * 4)   // 86016 B

__global__ __launch_bounds__(256, 2)
void sem_gemm_mma(const float* __restrict__ A, const float* __restrict__ Z,
                  const float* __restrict__ mask_f, float* __restrict__ out) {
    extern __shared__ float sm[];
    float* sAhi = sm;
    float* sAlo = sm + SEM_BK * SEM_STR;
    float* sBt  = sm + 2 * SEM_BK * SEM_STR;
    float* rawA = sm + SEM_STAGE_F;
    float* rawB = rawA + SEM_RAW_F;

    const int m    = blockIdx.x;
    const int aBlk = blockIdx.y;
    const int b    = blockIdx.z;
    const int tid  = threadIdx.x;
    const int w    = tid >> 5, lane = tid & 31;
    const int warpM = w >> 1, warpN = w & 1;
    const int g  = lane >> 2;
    const int kc = lane & 3;

    const float* Ab  = A + (long long)b * PN * PK + aBlk * 128;
    const float* Zb  = Z + (long long)b * PN * PN * PCZ + (long long)m * PCZ;
    const float* mfb = mask_f + b * PN;

    float acc[2][8][4];
#pragma unroll
    for (int mt = 0; mt < 2; ++mt)
#pragma unroll
        for (int nt = 0; nt < 8; ++nt)
#pragma unroll
            for (int q = 0; q < 4; ++q) acc[mt][nt][q] = 0.f;

    const int kloc = tid >> 3;     // 0..31 staging row
    const int asub = tid & 7;
    auto fill_chunk = [&](int c) {
        const int r = tid >> 3;
        const int n = c * SEM_BK + r;
        const float* gA = Ab + (long long)n * PK;
        const float* gB = Zb + (long long)n * (PN * PCZ);
#pragma unroll
        for (int i = 0; i < 4; ++i) {
            const int col = (asub + 8 * i) * 4;
            cp16(&rawA[r * SEM_RAWSTR + col], gA + col);
            cp16(&rawB[r * SEM_RAWSTR + col], gB + col);
        }
    };

    fill_chunk(0);
    CP_COMMIT();

    for (int c = 0; c < PK / SEM_BK; ++c) {
        CP_WAIT0();
        __syncthreads();            // raw(c) visible; MMA(c-1) readers done
        const float mf  = mfb[c * SEM_BK + kloc];
        const float mf2 = mf * mf;
#pragma unroll
        for (int j = 0; j < 16; ++j) {
            const int a = asub + 8 * j;
            float hi, lo;
            split_hl(rawA[kloc * SEM_RAWSTR + a] * mf2, hi, lo);
            sAhi[kloc * SEM_STR + a] = hi;
            sAlo[kloc * SEM_STR + a] = lo;
            sBt[kloc * SEM_STR + a]  = to_tf32_rn(rawB[kloc * SEM_RAWSTR + a]);
        }
        __syncthreads();            // staging ready; raw reads done
        if (c + 1 < PK / SEM_BK) { fill_chunk(c + 1); CP_COMMIT(); }

#pragma unroll
        for (int ks = 0; ks < SEM_BK / 8; ++ks) {
            const int k0 = ks * 8;
            uint32_t ah[2][4], al[2][4];
#pragma unroll
            for (int mt = 0; mt < 2; ++mt) {
                const int r0 = warpM * 32 + mt * 16 + g;
                ah[mt][0] = __float_as_uint(sAhi[(k0 + kc) * SEM_STR + r0]);
                ah[mt][1] = __float_as_uint(sAhi[(k0 + kc) * SEM_STR + r0 + 8]);
                ah[mt][2] = __float_as_uint(sAhi[(k0 + kc + 4) * SEM_STR + r0]);
                ah[mt][3] = __float_as_uint(sAhi[(k0 + kc + 4) * SEM_STR + r0 + 8]);
                al[mt][0] = __float_as_uint(sAlo[(k0 + kc) * SEM_STR + r0]);
                al[mt][1] = __float_as_uint(sAlo[(k0 + kc) * SEM_STR + r0 + 8]);
                al[mt][2] = __float_as_uint(sAlo[(k0 + kc + 4) * SEM_STR + r0]);
                al[mt][3] = __float_as_uint(sAlo[(k0 + kc + 4) * SEM_STR + r0 + 8]);
            }
#pragma unroll
            for (int nt = 0; nt < 8; ++nt) {
                const int cc = warpN * 64 + nt * 8 + g;
                uint32_t bt0 = __float_as_uint(sBt[(k0 + kc) * SEM_STR + cc]);
                uint32_t bt1 = __float_as_uint(sBt[(k0 + kc + 4) * SEM_STR + cc]);
#pragma unroll
                for (int mt = 0; mt < 2; ++mt) {
                    mma_tf32(acc[mt][nt], ah[mt], bt0, bt1);
                    mma_tf32(acc[mt][nt], al[mt], bt0, bt1);
                }
            }
        }
    }

    const float smv = g_s[b * PN + m];
    const float num = mfb[m] * smv;
#pragma unroll
    for (int mt = 0; mt < 2; ++mt) {
        const int a0r = aBlk * 128 + warpM * 32 + mt * 16 + g;
        const int a1r = a0r + 8;
        const float f0 = num / fmaxf(g_col[b * PK + a0r] * smv, F_EPS);
        const float f1 = num / fmaxf(g_col[b * PK + a1r] * smv, F_EPS);
        float* d0 = out + OFF_SEM + (((long long)(b * PK + a0r)) * PN + m) * PCZ;
        float* d1 = out + OFF_SEM + (((long long)(b * PK + a1r)) * PN + m) * PCZ;
#pragma unroll
        for (int nt = 0; nt < 8; ++nt) {
            const int cc = warpN * 64 + nt * 8 + 2 * kc;
            float2 v0, v1;
            v0.x = acc[mt][nt][0] * f0; v0.y = acc[mt][nt][1] * f0;
            v1.x = acc[mt][nt][2] * f1; v1.y = acc[mt][nt][3] * f1;
            *(float2*)(d0 + cc) = v0;
            *(float2*)(d1 + cc) = v1;
        }
    }
}

// ---------------- K2: geometry RBF ----------------
__global__ void geo_kernel(const float* __restrict__ mu,
                           const float* __restrict__ mask_c,
                           float* __restrict__ out) {
    int idx = blockIdx.x * 256 + threadIdx.x;
    if (idx >= PB * PK * PK) return;
    int b = idx / (PK * PK);
    int r = idx - b * PK * PK;
    int i = r / PK, j = r - i * PK;
    const float* mi = mu + ((long long)b * PK + i) * 3;
    const float* mj = mu + ((long long)b * PK + j) * 3;
    float dx = mi[0] - mj[0], dy = mi[1] - mj[1], dz = mi[2] - mj[2];
    float d = sqrtf(dx * dx + dy * dy + dz * dz + F_EPS);
    float mc2 = mask_c[b * PK + i] * mask_c[b * PK + j];
    const float width = F_DMAX / (PBINS - 1);
    const float invw  = (PBINS - 1) / F_DMAX;
    float* dst = out + OFF_GEO + (long long)idx * PBINS;
#pragma unroll
    for (int t = 0; t < PBINS; t += 4) {
        float4 v;
        float u;
        u = (d - (t + 0) * width) * invw; v.x = __expf(-0.5f * u * u) * mc2;
        u = (d - (t + 1) * width) * invw; v.y = __expf(-0.5f * u * u) * mc2;
        u = (d - (t + 2) * width) * invw; v.z = __expf(-0.5f * u * u) * mc2;
        u = (d - (t + 3) * width) * invw; v.w = __expf(-0.5f * u * u) * mc2;
        *(float4*)(dst + t) = v;
    }
}

// ---------------- K3: fused MLP, cp.async + 2-MMA split ----------------------
// activations split exactly; W1/W2 rounded to tf32 (rn).
#define MLP_STR 136
#define MLP_CH 16
#define MLP_STAGE (MLP_CH * MLP_STR)               // 2176 floats per array
#define MLP_RAWSTR 20
#define MLP_RAW_F (128 * MLP_RAWSTR)               // 2560 floats
#define SG_STRIDE 132
#define SMEM_MLP_FLOATS (3 * MLP_STAGE + 128 * SG_STRIDE + MLP_RAW_F)  // 25984 f

__global__ __launch_bounds__(256, 2) void mlp_mma(
    float* __restrict__ out,
    const float* __restrict__ W1, const float* __restrict__ b1,
    const float* __restrict__ lng, const float* __restrict__ lnb,
    const float* __restrict__ W2, const float* __restrict__ b2,
    const float* __restrict__ mask_c) {
    extern __shared__ float sm[];
    float* sAhi = sm;
    float* sAlo = sm + MLP_STAGE;
    float* sBt  = sm + 2 * MLP_STAGE;
    float* sG   = sm + 3 * MLP_STAGE;          // 128 x SG_STRIDE
    float* rawX = sG + 128 * SG_STRIDE;        // 128 x MLP_RAWSTR

    const int row0 = blockIdx.x * 128;
    const int tid  = threadIdx.x;
    const int w    = tid >> 5, lane = tid & 31;
    const int warpM = w >> 1, warpN = w & 1;
    const int g  = lane >> 2;
    const int kc = lane & 3;
    const float* sem = out + OFF_SEM;
    const float* geo = out + OFF_GEO;

    const int sr = tid >> 1;            // 0..127 row
    const int sk = (tid & 1) * 8;       // 0 or 8
    const int ky = tid >> 4, cx = tid & 15;   // W staging map

    float acc[2][8][4];
#pragma unroll
    for (int mt = 0; mt < 2; ++mt)
#pragma unroll
        for (int nt = 0; nt < 8; ++nt)
#pragma unroll
            for (int q = 0; q < 4; ++q) acc[mt][nt][q] = 0.f;

    auto fillX = [&](int c) {
        const int r = tid >> 1;
        const int j = tid & 1;
        const float* p = (c < 8)
            ? sem + (long long)(row0 + r) * PCZ + c * MLP_CH
            : geo + (long long)(row0 + r) * PBINS;
        cp16(&rawX[r * MLP_RAWSTR + j * 4],     p + j * 4);
        cp16(&rawX[r * MLP_RAWSTR + j * 4 + 8], p + j * 4 + 8);
    };

    fillX(0);
    CP_COMMIT();

    // ---- GEMM1: X[128x144] @ W1[144x128] ----
    for (int c = 0; c < PCIN / MLP_CH; ++c) {
        CP_WAIT0();
        __syncthreads();
        {
            const float* p = &rawX[sr * MLP_RAWSTR + sk];
#pragma unroll
            for (int i = 0; i < 8; ++i) {
                float hi, lo;
                split_hl(p[i], hi, lo);
                sAhi[(sk + i) * MLP_STR + sr] = hi;
                sAlo[(sk + i) * MLP_STR + sr] = lo;
            }
            const float* q = W1 + (long long)(c * MLP_CH + ky) * PCOUT + cx * 8;
            float4 w0 = *(const float4*)q;
            float4 w1 = *(const float4*)(q + 4);
            float ww[8] = {w0.x, w0.y, w0.z, w0.w, w1.x, w1.y, w1.z, w1.w};
#pragma unroll
            for (int i = 0; i < 8; ++i)
                sBt[ky * MLP_STR + cx * 8 + i] = to_tf32_rn(ww[i]);
        }
        __syncthreads();
        if (c + 1 < PCIN / MLP_CH) { fillX(c + 1); CP_COMMIT(); }

#pragma unroll
        for (int ks = 0; ks < MLP_CH / 8; ++ks) {
            const int k0 = ks * 8;
            uint32_t ah[2][4], al[2][4];
#pragma unroll
            for (int mt = 0; mt < 2; ++mt) {
                const int r0 = warpM * 32 + mt * 16 + g;
                ah[mt][0] = __float_as_uint(sAhi[(k0 + kc) * MLP_STR + r0]);
                ah[mt][1] = __float_as_uint(sAhi[(k0 + kc) * MLP_STR + r0 + 8]);
                ah[mt][2] = __float_as_uint(sAhi[(k0 + kc + 4) * MLP_STR + r0]);
                ah[mt][3] = __float_as_uint(sAhi[(k0 + kc + 4) * MLP_STR + r0 + 8]);
                al[mt][0] = __float_as_uint(sAlo[(k0 + kc) * MLP_STR + r0]);
                al[mt][1] = __float_as_uint(sAlo[(k0 + kc) * MLP_STR + r0 + 8]);
                al[mt][2] = __float_as_uint(sAlo[(k0 + kc + 4) * MLP_STR + r0]);
                al[mt][3] = __float_as_uint(sAlo[(k0 + kc + 4) * MLP_STR + r0 + 8]);
            }
#pragma unroll
            for (int nt = 0; nt < 8; ++nt) {
                const int cc = warpN * 64 + nt * 8 + g;
                uint32_t bt0 = __float_as_uint(sBt[(k0 + kc) * MLP_STR + cc]);
                uint32_t bt1 = __float_as_uint(sBt[(k0 + kc + 4) * MLP_STR + cc]);
#pragma unroll
                for (int mt = 0; mt < 2; ++mt) {
                    mma_tf32(acc[mt][nt], ah[mt], bt0, bt1);
                    mma_tf32(acc[mt][nt], al[mt], bt0, bt1);
                }
            }
        }
    }
    __syncthreads();

    // ---- write h = acc + b1 into sG (fragment layout) ----
#pragma unroll
    for (int mt = 0; mt < 2; ++mt) {
        const int r0 = warpM * 32 + mt * 16 + g;
#pragma unroll
        for (int nt = 0; nt < 8; ++nt) {
            const int cc = warpN * 64 + nt * 8 + 2 * kc;
            float2 bb = *(const float2*)(b1 + cc);
            float2 v0, v1;
            v0.x = acc[mt][nt][0] + bb.x; v0.y = acc[mt][nt][1] + bb.y;
            v1.x = acc[mt][nt][2] + bb.x; v1.y = acc[mt][nt][3] + bb.y;
            *(float2*)&sG[r0 * SG_STRIDE + cc]       = v0;
            *(float2*)&sG[(r0 + 8) * SG_STRIDE + cc] = v1;
        }
    }
    __syncthreads();

    // ---- LayerNorm + SiLU, one thread per row ----
    if (tid < 128) {
        float* gr = &sG[tid * SG_STRIDE];
        float s = 0.f;
#pragma unroll 8
        for (int c = 0; c < 128; ++c) s += gr[c];
        float mu = s * (1.f / 128.f);
        float vs = 0.f;
#pragma unroll 8
        for (int c = 0; c < 128; ++c) { float dd = gr[c] - mu; vs = fmaf(dd, dd, vs); }
        float rstd = rsqrtf(vs * (1.f / 128.f) + F_LNEPS);
#pragma unroll 8
        for (int c = 0; c < 128; ++c) {
            float x = (gr[c] - mu) * rstd * lng[c] + lnb[c];
            gr[c] = x / (1.f + __expf(-x));
        }
    }

    // ---- GEMM2: silu(h)[128x128] @ W2[128x128] (A from sG) ----
    float acc2[2][8][4];
#pragma unroll
    for (int mt = 0; mt < 2; ++mt)
#pragma unroll
        for (int nt = 0; nt < 8; ++nt)
#pragma unroll
            for (int q = 0; q < 4; ++q) acc2[mt][nt][q] = 0.f;

    for (int c = 0; c < PCOUT / MLP_CH; ++c) {
        __syncthreads();
        {
            const float* p = &sG[sr * SG_STRIDE + c * MLP_CH + sk];
#pragma unroll
            for (int i = 0; i < 8; ++i) {
                float hi, lo;
                split_hl(p[i], hi, lo);
                sAhi[(sk + i) * MLP_STR + sr] = hi;
                sAlo[(sk + i) * MLP_STR + sr] = lo;
            }
            const float* q = W2 + (long long)(c * MLP_CH + ky) * PCOUT + cx * 8;
            float4 w0 = *(const float4*)q;
            float4 w1 = *(const float4*)(q + 4);
            float ww[8] = {w0.x, w0.y, w0.z, w0.w, w1.x, w1.y, w1.z, w1.w};
#pragma unroll
            for (int i = 0; i < 8; ++i)
                sBt[ky * MLP_STR + cx * 8 + i] = to_tf32_rn(ww[i]);
        }
        __syncthreads();
#pragma unroll
        for (int ks = 0; ks < MLP_CH / 8; ++ks) {
            const int k0 = ks * 8;
            uint32_t ah[2][4], al[2][4];
#pragma unroll
            for (int mt = 0; mt < 2; ++mt) {
                const int r0 = warpM * 32 + mt * 16 + g;
                ah[mt][0] = __float_as_uint(sAhi[(k0 + kc) * MLP_STR + r0]);
                ah[mt][1] = __float_as_uint(sAhi[(k0 + kc) * MLP_STR + r0 + 8]);
                ah[mt][2] = __float_as_uint(sAhi[(k0 + kc + 4) * MLP_STR + r0]);
                ah[mt][3] = __float_as_uint(sAhi[(k0 + kc + 4) * MLP_STR + r0 + 8]);
                al[mt][0] = __float_as_uint(sAlo[(k0 + kc) * MLP_STR + r0]);
                al[mt][1] = __float_as_uint(sAlo[(k0 + kc) * MLP_STR + r0 + 8]);
                al[mt][2] = __float_as_uint(sAlo[(k0 + kc + 4) * MLP_STR + r0]);
                al[mt][3] = __float_as_uint(sAlo[(k0 + kc + 4) * MLP_STR + r0 + 8]);
            }
#pragma unroll
            for (int nt = 0; nt < 8; ++nt) {
                const int cc = warpN * 64 + nt * 8 + g;
                uint32_t bt0 = __float_as_uint(sBt[(k0 + kc) * MLP_STR + cc]);
                uint32_t bt1 = __float_as_uint(sBt[(k0 + kc + 4) * MLP_STR + cc]);
#pragma unroll
                for (int mt = 0; mt < 2; ++mt) {
                    mma_tf32(acc2[mt][nt], ah[mt], bt0, bt1);
                    mma_tf32(acc2[mt][nt], al[mt], bt0, bt1);
                }
            }
        }
    }

    // ---- epilogue: +b2, *mc2, write Z_c ----
#pragma unroll
    for (int mt = 0; mt < 2; ++mt) {
        const int rg0 = row0 + warpM * 32 + mt * 16 + g;
        const int rg1 = rg0 + 8;
        int bb0 = rg0 / (PK * PK), rr0 = rg0 - bb0 * PK * PK;
        int bb1 = rg1 / (PK * PK), rr1 = rg1 - bb1 * PK * PK;
        int i0 = rr0 / PK, j0 = rr0 - i0 * PK;
        int i1 = rr1 / PK, j1 = rr1 - i1 * PK;
        const float mc0 = mask_c[bb0 * PK + i0] * mask_c[bb0 * PK + j0];
        const float mc1 = mask_c[bb1 * PK + i1] * mask_c[bb1 * PK + j1];
        float* d0 = out + (long long)rg0 * PCOUT;
        float* d1 = out + (long long)rg1 * PCOUT;
#pragma unroll
        for (int nt = 0; nt < 8; ++nt) {
            const int cc = warpN * 64 + nt * 8 + 2 * kc;
            float2 bb = *(const float2*)(b2 + cc);
            float2 v0, v1;
            v0.x = (acc2[mt][nt][0] + bb.x) * mc0; v0.y = (acc2[mt][nt][1] + bb.y) * mc0;
            v1.x = (acc2[mt][nt][2] + bb.x) * mc1; v1.y = (acc2[mt][nt][3] + bb.y) * mc1;
            *(float2*)(d0 + cc) = v0;
            *(float2*)(d1 + cc) = v1;
        }
    }
}

// ---------------- launch ----------------
extern "C" void kernel_launch(void* const* d_in, const int* in_sizes, int n_in,
                              void* d_out, int out_size) {
    const float* A      = (const float*)d_in[0];
    const float* Zf     = (const float*)d_in[1];
    const float* mu     = (const float*)d_in[2];
    const float* mask_f = (const float*)d_in[3];
    const float* mask_c = (const float*)d_in[4];
    const float* W1     = (const float*)d_in[5];
    const float* b1     = (const float*)d_in[6];
    const float* lng    = (const float*)d_in[7];
    const float* lnb    = (const float*)d_in[8];
    const float* W2     = (const float*)d_in[9];
    const float* b2     = (const float*)d_in[10];
    float* out = (float*)d_out;

    const int smem_mlp = SMEM_MLP_FLOATS * (int)sizeof(float);
    cudaFuncSetAttribute(mlp_mma, cudaFuncAttributeMaxDynamicSharedMemorySize, smem_mlp);
    cudaFuncSetAttribute(sem_gemm_mma, cudaFuncAttributeMaxDynamicSharedMemorySize, SEM_SMEM_BYTES);

    reduce_kernel<<<dim3(PB, 2), PK>>>(A, mask_f);
    sem_gemm_mma<<<dim3(PN, 3, PB), 256, SEM_SMEM_BYTES>>>(A, Zf, mask_f, out);
    geo_kernel<<<(PB * PK * PK + 255) / 256, 256>>>(mu, mask_c, out);
    mlp_mma<<<PB * PK * PK / 128, 256, smem_mlp>>>(out, W1, b1, lng, lnb, W2, b2, mask_c);
}